// round 8
// baseline (speedup 1.0000x reference)
#include <cuda_runtime.h>
#include <cuda_fp16.h>
#include <cuda_bf16.h>
#include <cstdint>

// Problem constants
#define T_   16
#define B_   128
#define N_   2048
#define TB_  (T_ * B_)          // 2048 rows
#define BN_  (B_ * N_)          // 262144

// ---------------- scratch (device globals; no allocs allowed) --------------
__device__ float  g_h[TB_ * N_];         // GEMM output h [TB, N] (16 MB)
__device__ __half g_ah[TB_ * N_];        // A = x  fp16 hi plane (8 MB)
__device__ __half g_al[TB_ * N_];        // A lo plane
__device__ __half g_wh[N_ * N_];         // W hi plane
__device__ __half g_wl[N_ * N_];         // W lo plane
__device__ float  g_sspart[T_ * 256];    // spatial_sum partials [T][256] (2/b)
__device__ float  g_tsump[4 * BN_];      // temporal_sum partials (4 t-groups)
__device__ float  g_colsum[N_];          // BN column sums (atomic)
__device__ float  g_colsq[N_];           // BN column sums of squares

// ======================= helpers ===========================================
__device__ __forceinline__ uint32_t smem_u32(const void* p) {
    uint32_t a;
    asm("{ .reg .u64 t; cvta.to.shared.u64 t, %1; cvt.u32.u64 %0, t; }"
        : "=r"(a) : "l"(p));
    return a;
}

__device__ __forceinline__ void ldsm_x4(uint32_t addr, uint32_t& r0, uint32_t& r1,
                                        uint32_t& r2, uint32_t& r3) {
    asm volatile("ldmatrix.sync.aligned.m8n8.x4.shared.b16 {%0,%1,%2,%3}, [%4];"
                 : "=r"(r0), "=r"(r1), "=r"(r2), "=r"(r3) : "r"(addr));
}

__device__ __forceinline__ void mma_fp16(float* c, const uint32_t* a,
                                         uint32_t b0, uint32_t b1) {
    asm volatile(
        "mma.sync.aligned.m16n8k16.row.col.f32.f16.f16.f32 "
        "{%0,%1,%2,%3}, {%4,%5,%6,%7}, {%8,%9}, {%0,%1,%2,%3};\n"
        : "+f"(c[0]), "+f"(c[1]), "+f"(c[2]), "+f"(c[3])
        : "r"(a[0]), "r"(a[1]), "r"(a[2]), "r"(a[3]), "r"(b0), "r"(b1));
}

#define CP_ASYNC16(dst, src) \
    asm volatile("cp.async.ca.shared.global [%0], [%1], 16;" :: "r"(dst), "l"(src))
#define CP_COMMIT() asm volatile("cp.async.commit_group;" ::: "memory")
#define CP_WAIT1()  asm volatile("cp.async.wait_group 1;" ::: "memory")

// split float4 into fp16 hi / fp16 lo (each packed as 2x half2 -> uint2)
__device__ __forceinline__ void split4h(float4 v, uint2& hi, uint2& lo) {
    __half hx = __float2half_rn(v.x);
    __half hy = __float2half_rn(v.y);
    __half hz = __float2half_rn(v.z);
    __half hw = __float2half_rn(v.w);
    __half lx = __float2half_rn(v.x - __half2float(hx));
    __half ly = __float2half_rn(v.y - __half2float(hy));
    __half lz = __float2half_rn(v.z - __half2float(hz));
    __half lw = __float2half_rn(v.w - __half2float(hw));
    __half2 h01 = __halves2half2(hx, hy);
    __half2 h23 = __halves2half2(hz, hw);
    __half2 l01 = __halves2half2(lx, ly);
    __half2 l23 = __halves2half2(lz, lw);
    hi.x = *reinterpret_cast<uint32_t*>(&h01);
    hi.y = *reinterpret_cast<uint32_t*>(&h23);
    lo.x = *reinterpret_cast<uint32_t*>(&l01);
    lo.y = *reinterpret_cast<uint32_t*>(&l23);
}

// ======================= K1: fused prep (balanced blocks) ===================
// blocks [0,1024):    x split for 4 timesteps -> g_ah/g_al, temporal partial
//                     plane, spatial-sum partials. blocks 0..7 zero BN accums.
// blocks [1024,2048): W split, 4 float4 per thread.
__global__ __launch_bounds__(256)
void prep_kernel(const float* __restrict__ x, const float* __restrict__ W) {
    const int tid = threadIdx.x;
    if (blockIdx.x >= 1024) {
        int base = (blockIdx.x - 1024) * 1024;
        #pragma unroll
        for (int i = 0; i < 4; i++) {
            int idx4 = base + i * 256 + tid;
            float4 v = reinterpret_cast<const float4*>(W)[idx4];
            uint2 hi, lo;
            split4h(v, hi, lo);
            reinterpret_cast<uint2*>(g_wh)[idx4] = hi;
            reinterpret_cast<uint2*>(g_wl)[idx4] = lo;
        }
        return;
    }

    // ---- x-side block: t-group tq (4 timesteps), column block cb ----
    const int tq = blockIdx.x >> 8;              // 0..3
    const int cb = blockIdx.x & 255;             // 0..255
    if (blockIdx.x < 8) {
        g_colsum[blockIdx.x * 256 + tid] = 0.f;
        g_colsq [blockIdx.x * 256 + tid] = 0.f;
    }

    __shared__ float red[4][8];
    const int idx4 = cb * 256 + tid;             // float4 index into [B,N]
    const int wid  = tid >> 5;
    const int lane = tid & 31;
    const float4* x4 = reinterpret_cast<const float4*>(x);
    uint2* ah2 = reinterpret_cast<uint2*>(g_ah);
    uint2* al2 = reinterpret_cast<uint2*>(g_al);

    float4 ts = make_float4(0.f, 0.f, 0.f, 0.f);
    #pragma unroll
    for (int tt = 0; tt < 4; tt++) {
        int t = tq * 4 + tt;
        size_t off = (size_t)t * (BN_ / 4) + idx4;
        float4 v = x4[off];
        ts.x += v.x; ts.y += v.y; ts.z += v.z; ts.w += v.w;
        uint2 hi, lo;
        split4h(v, hi, lo);
        ah2[off] = hi;
        al2[off] = lo;
        float s = v.x + v.y + v.z + v.w;
        #pragma unroll
        for (int o = 16; o > 0; o >>= 1)
            s += __shfl_down_sync(0xffffffffu, s, o);
        if (lane == 0) red[tt][wid] = s;
    }
    reinterpret_cast<float4*>(g_tsump)[tq * (BN_ / 4) + idx4] = ts;
    __syncthreads();
    if (tid < 4) {
        float s = 0.f;
        #pragma unroll
        for (int w = 0; w < 8; w++) s += red[tid][w];
        g_sspart[(tq * 4 + tid) * 256 + cb] = s;
    }
}

// ======================= K2: mma.sync fp16x3 GEMM (64x64 tiles) =============
// h[r,m] = sum_k x[r,k] * W[m,k].
// CTA tile 64(M) x 64(N) x 32(K), 128 threads = 4 warps (2x2), warp 32x32.
// 1024 CTAs -> multi-wave work-stealing fixes the 86.5% occupancy imbalance.
#define BK      32
#define HPITCH  40                      // halfs per smem row (32 + 8 pad)
#define PLANEB  (64 * HPITCH * 2)       // 5120 bytes per plane
#define STAGEB  (4 * PLANEB)            // A_hi, A_lo, B_hi, B_lo: 20480 B
#define GEMM_SMEM (2 * STAGEB)          // 40960 bytes

__global__ __launch_bounds__(128, 4)
void gemm_mma_kernel(float* __restrict__ C) {
    extern __shared__ char smc[];
    const uint32_t sbase = smem_u32(smc);
    const int tid  = threadIdx.x;
    const int wid  = tid >> 5;
    const int lane = tid & 31;
    const int wm = wid >> 1;            // 0..1 -> 32-row slab
    const int wn = wid & 1;             // 0..1 -> 32-col slab
    const int rowBase = blockIdx.y * 64;
    const int colBase = blockIdx.x * 64;

    float acc[2][4][4];
    #pragma unroll
    for (int i = 0; i < 2; i++)
        #pragma unroll
        for (int j = 0; j < 4; j++)
            #pragma unroll
            for (int c = 0; c < 4; c++) acc[i][j][c] = 0.f;

    // ---- cp.async loader: thread -> (row, 16-half part) ----
    const int lrow = tid >> 1;                  // 0..63
    const int part = (tid & 1) * 16;            // half offset within row
    const __half* pAh = g_ah + (size_t)(rowBase + lrow) * N_ + part;
    const __half* pAl = g_al + (size_t)(rowBase + lrow) * N_ + part;
    const __half* pBh = g_wh + (size_t)(colBase + lrow) * N_ + part;
    const __half* pBl = g_wl + (size_t)(colBase + lrow) * N_ + part;
    const uint32_t dRow = (uint32_t)((lrow * HPITCH + part) * 2);

    // ---- ldmatrix per-lane byte offsets ----
    const uint32_t aLane = (uint32_t)((((lane & 15) * HPITCH) + (lane >> 4) * 8) * 2);
    const uint32_t bLane = (uint32_t)(((((lane & 7) + ((lane >> 4) & 1) * 8) * HPITCH)
                                       + ((lane >> 3) & 1) * 8) * 2);
    const uint32_t aBase = sbase + (uint32_t)((wm * 32) * HPITCH * 2) + aLane;
    const uint32_t bBase = sbase + 2 * PLANEB + (uint32_t)((wn * 32) * HPITCH * 2) + bLane;

    // ---- prologue: load chunks 0,1 ----
    #pragma unroll
    for (int s = 0; s < 2; s++) {
        const uint32_t d = sbase + s * STAGEB + dRow;
        const int ko = s * BK;
        CP_ASYNC16(d,                       pAh + ko);
        CP_ASYNC16(d + 16,                  pAh + ko + 8);
        CP_ASYNC16(d + PLANEB,              pAl + ko);
        CP_ASYNC16(d + PLANEB + 16,         pAl + ko + 8);
        CP_ASYNC16(d + 2 * PLANEB,          pBh + ko);
        CP_ASYNC16(d + 2 * PLANEB + 16,     pBh + ko + 8);
        CP_ASYNC16(d + 3 * PLANEB,          pBl + ko);
        CP_ASYNC16(d + 3 * PLANEB + 16,     pBl + ko + 8);
        CP_COMMIT();
    }

    const int NCHUNK = N_ / BK;          // 64
    #pragma unroll 1
    for (int kc = 0; kc < NCHUNK; kc++) {
        const int st = kc & 1;
        CP_WAIT1();
        __syncthreads();

        const uint32_t aS = aBase + st * STAGEB;
        const uint32_t bS = bBase + st * STAGEB;

        #pragma unroll
        for (int ks = 0; ks < 2; ks++) {
            const uint32_t kb = ks * 32;   // 16 halfs = 32 bytes
            uint32_t bh[2][4], bl[2][4];
            #pragma unroll
            for (int jp = 0; jp < 2; jp++) {
                ldsm_x4(bS + kb + jp * (16 * HPITCH * 2),
                        bh[jp][0], bh[jp][1], bh[jp][2], bh[jp][3]);
                ldsm_x4(bS + PLANEB + kb + jp * (16 * HPITCH * 2),
                        bl[jp][0], bl[jp][1], bl[jp][2], bl[jp][3]);
            }
            #pragma unroll
            for (int i = 0; i < 2; i++) {
                uint32_t ah[4], al[4];
                ldsm_x4(aS + kb + i * (16 * HPITCH * 2), ah[0], ah[1], ah[2], ah[3]);
                ldsm_x4(aS + PLANEB + kb + i * (16 * HPITCH * 2), al[0], al[1], al[2], al[3]);
                #pragma unroll
                for (int j = 0; j < 4; j++)
                    mma_fp16(acc[i][j], ah, bh[j >> 1][(j & 1) * 2], bh[j >> 1][(j & 1) * 2 + 1]);
                #pragma unroll
                for (int j = 0; j < 4; j++)
                    mma_fp16(acc[i][j], al, bh[j >> 1][(j & 1) * 2], bh[j >> 1][(j & 1) * 2 + 1]);
                #pragma unroll
                for (int j = 0; j < 4; j++)
                    mma_fp16(acc[i][j], ah, bl[j >> 1][(j & 1) * 2], bl[j >> 1][(j & 1) * 2 + 1]);
            }
        }
        __syncthreads();

        // refill the consumed stage with chunk kc+2
        if (kc + 2 < NCHUNK) {
            const uint32_t d = sbase + st * STAGEB + dRow;
            const int ko = (kc + 2) * BK;
            CP_ASYNC16(d,                       pAh + ko);
            CP_ASYNC16(d + 16,                  pAh + ko + 8);
            CP_ASYNC16(d + PLANEB,              pAl + ko);
            CP_ASYNC16(d + PLANEB + 16,         pAl + ko + 8);
            CP_ASYNC16(d + 2 * PLANEB,          pBh + ko);
            CP_ASYNC16(d + 2 * PLANEB + 16,     pBh + ko + 8);
            CP_ASYNC16(d + 3 * PLANEB,          pBl + ko);
            CP_ASYNC16(d + 3 * PLANEB + 16,     pBl + ko + 8);
        }
        CP_COMMIT();
    }

    // ---- epilogue: write 64x64 tile + fused BN column stats ----
    const int gid = lane >> 2;
    const int qd  = lane & 3;
    const int m0 = rowBase + wm * 32 + gid;
    const int n0 = colBase + wn * 32 + 2 * qd;
    #pragma unroll
    for (int i = 0; i < 2; i++) {
        #pragma unroll
        for (int jj = 0; jj < 4; jj++) {
            float* p = C + (size_t)(m0 + 16 * i) * N_ + n0 + 8 * jj;
            float2 v01 = make_float2(acc[i][jj][0], acc[i][jj][1]);
            float2 v23 = make_float2(acc[i][jj][2], acc[i][jj][3]);
            *reinterpret_cast<float2*>(p)          = v01;
            *reinterpret_cast<float2*>(p + 8 * N_) = v23;
        }
    }

    // column sums / sums-of-squares over this warp's 32 rows
    float s[4][2], q[4][2];
    #pragma unroll
    for (int j = 0; j < 4; j++) {
        s[j][0] = s[j][1] = q[j][0] = q[j][1] = 0.f;
        #pragma unroll
        for (int i = 0; i < 2; i++) {
            s[j][0] += acc[i][j][0] + acc[i][j][2];
            s[j][1] += acc[i][j][1] + acc[i][j][3];
            q[j][0] += acc[i][j][0] * acc[i][j][0] + acc[i][j][2] * acc[i][j][2];
            q[j][1] += acc[i][j][1] * acc[i][j][1] + acc[i][j][3] * acc[i][j][3];
        }
    }
    #pragma unroll
    for (int j = 0; j < 4; j++)
        #pragma unroll
        for (int c = 0; c < 2; c++) {
            #pragma unroll
            for (int off = 16; off >= 4; off >>= 1) {
                s[j][c] += __shfl_down_sync(0xffffffffu, s[j][c], off);
                q[j][c] += __shfl_down_sync(0xffffffffu, q[j][c], off);
            }
        }
    if (lane < 4) {
        #pragma unroll
        for (int j = 0; j < 4; j++)
            #pragma unroll
            for (int c = 0; c < 2; c++) {
                int col = colBase + wn * 32 + 2 * lane + 8 * j + c;
                atomicAdd(&g_colsum[col], s[j][c]);
                atomicAdd(&g_colsq[col],  q[j][c]);
            }
    }
}

// ======================= K3: fused BN + 3x LIF + combine ====================
__global__ __launch_bounds__(256)
void fused_lif_kernel(const float* __restrict__ x,
                      const float* __restrict__ gamma,
                      const float* __restrict__ beta,
                      float* __restrict__ out) {
    int idx4 = blockIdx.x * 256 + threadIdx.x;   // float4 index into [B,N]
    int b  = idx4 >> 9;
    int n4 = idx4 & 511;

    float4 cs4 = reinterpret_cast<const float4*>(g_colsum)[n4];
    float4 cq4 = reinterpret_cast<const float4*>(g_colsq)[n4];
    float4 ga4 = reinterpret_cast<const float4*>(gamma)[n4];
    float4 be4 = reinterpret_cast<const float4*>(beta)[n4];

    // temporal_sum = sum of 4 partial planes
    float4 ts4 = make_float4(0.f, 0.f, 0.f, 0.f);
    #pragma unroll
    for (int p = 0; p < 4; p++) {
        float4 v = reinterpret_cast<const float4*>(g_tsump)[p * (BN_ / 4) + idx4];
        ts4.x += v.x; ts4.y += v.y; ts4.z += v.z; ts4.w += v.w;
    }

    const float inv = 1.0f / TB_;
    float mu[4]    = {cs4.x * inv, cs4.y * inv, cs4.z * inv, cs4.w * inv};
    float var[4]   = {cq4.x * inv - mu[0] * mu[0], cq4.y * inv - mu[1] * mu[1],
                      cq4.z * inv - mu[2] * mu[2], cq4.w * inv - mu[3] * mu[3]};
    float scale[4] = {ga4.x * rsqrtf(var[0] + 1e-5f), ga4.y * rsqrtf(var[1] + 1e-5f),
                      ga4.z * rsqrtf(var[2] + 1e-5f), ga4.w * rsqrtf(var[3] + 1e-5f)};
    float bet[4]   = {be4.x, be4.y, be4.z, be4.w};
    float ts[4]    = {ts4.x, ts4.y, ts4.z, ts4.w};

    float v1[4] = {0, 0, 0, 0}, v2[4] = {0, 0, 0, 0}, v3[4] = {0, 0, 0, 0};
    const float4* h4 = reinterpret_cast<const float4*>(g_h);
    const float4* x4 = reinterpret_cast<const float4*>(x);
    float4* o4 = reinterpret_cast<float4*>(out);

    #pragma unroll
    for (int t = 0; t < T_; t++) {
        size_t off = (size_t)t * (BN_ / 4) + idx4;
        float4 hv = h4[off];
        float4 xv = x4[off];
        float hh[4] = {hv.x, hv.y, hv.z, hv.w};
        float xx[4] = {xv.x, xv.y, xv.z, xv.w};
        float ss = g_sspart[t * 256 + b * 2] + g_sspart[t * 256 + b * 2 + 1];
        float res[4];
        #pragma unroll
        for (int j = 0; j < 4; j++) {
            float hn = (hh[j] - mu[j]) * scale[j] + bet[j];
            v1[j] = 0.5f * v1[j] + hn;
            float s1 = (v1[j] >= 1.0f) ? 1.0f : 0.0f;
            v1[j] = (v1[j] >= 1.0f) ? 0.0f : v1[j];
            v2[j] = 0.5f * v2[j] + s1 * ss;
            float s2 = (v2[j] >= 1.0f) ? 1.0f : 0.0f;
            v2[j] = (v2[j] >= 1.0f) ? 0.0f : v2[j];
            v3[j] = 0.5f * v3[j] + s1 * ts[j];
            float s3 = (v3[j] >= 1.0f) ? 1.0f : 0.0f;
            v3[j] = (v3[j] >= 1.0f) ? 0.0f : v3[j];
            res[j] = xx[j] + s2 * s3;
        }
        o4[off] = make_float4(res[0], res[1], res[2], res[3]);
    }
}

// ======================= launch =============================================
extern "C" void kernel_launch(void* const* d_in, const int* in_sizes, int n_in,
                              void* d_out, int out_size) {
    const float* x     = (const float*)d_in[0];   // [T,B,N]
    const float* W     = (const float*)d_in[1];   // [N,N]
    const float* gamma = (const float*)d_in[2];
    const float* beta  = (const float*)d_in[3];
    float* out = (float*)d_out;

    float* h;
    cudaGetSymbolAddress((void**)&h, g_h);

    cudaFuncSetAttribute(gemm_mma_kernel,
                         cudaFuncAttributeMaxDynamicSharedMemorySize, GEMM_SMEM);

    prep_kernel<<<2048, 256>>>(x, W);

    dim3 gemmGrid(N_ / 64, TB_ / 64);             // 32 x 32 = 1024 CTAs
    gemm_mma_kernel<<<gemmGrid, 128, GEMM_SMEM>>>(h);

    fused_lif_kernel<<<BN_ / 1024, 256>>>(x, gamma, beta, out);
}

// round 9
// speedup vs baseline: 1.3940x; 1.3940x over previous
#include <cuda_runtime.h>
#include <cuda_fp16.h>
#include <cuda_bf16.h>
#include <cstdint>

// Problem constants
#define T_   16
#define B_   128
#define N_   2048
#define TB_  (T_ * B_)          // 2048 rows
#define BN_  (B_ * N_)          // 262144

// ---------------- scratch (device globals; no allocs allowed) --------------
__device__ float  g_h[TB_ * N_];         // GEMM output h [TB, N] (16 MB)
__device__ __half g_ah[TB_ * N_];        // A = x  fp16 hi plane (8 MB)
__device__ __half g_al[TB_ * N_];        // A lo plane
__device__ __half g_wh[N_ * N_];         // W hi plane
__device__ __half g_wl[N_ * N_];         // W lo plane
__device__ float  g_sspart[T_ * 256];    // spatial_sum partials [T][256] (2/b)
__device__ float  g_tsump[4 * BN_];      // temporal_sum partials (4 t-groups)
__device__ float  g_colsum[N_];          // BN column sums (atomic)
__device__ float  g_colsq[N_];           // BN column sums of squares

// ======================= helpers ===========================================
__device__ __forceinline__ uint32_t smem_u32(const void* p) {
    uint32_t a;
    asm("{ .reg .u64 t; cvta.to.shared.u64 t, %1; cvt.u32.u64 %0, t; }"
        : "=r"(a) : "l"(p));
    return a;
}

__device__ __forceinline__ void ldsm_x4(uint32_t addr, uint32_t& r0, uint32_t& r1,
                                        uint32_t& r2, uint32_t& r3) {
    asm volatile("ldmatrix.sync.aligned.m8n8.x4.shared.b16 {%0,%1,%2,%3}, [%4];"
                 : "=r"(r0), "=r"(r1), "=r"(r2), "=r"(r3) : "r"(addr));
}

__device__ __forceinline__ void mma_fp16(float* c, const uint32_t* a,
                                         uint32_t b0, uint32_t b1) {
    asm volatile(
        "mma.sync.aligned.m16n8k16.row.col.f32.f16.f16.f32 "
        "{%0,%1,%2,%3}, {%4,%5,%6,%7}, {%8,%9}, {%0,%1,%2,%3};\n"
        : "+f"(c[0]), "+f"(c[1]), "+f"(c[2]), "+f"(c[3])
        : "r"(a[0]), "r"(a[1]), "r"(a[2]), "r"(a[3]), "r"(b0), "r"(b1));
}

#define CP_ASYNC16(dst, src) \
    asm volatile("cp.async.ca.shared.global [%0], [%1], 16;" :: "r"(dst), "l"(src))
#define CP_COMMIT() asm volatile("cp.async.commit_group;" ::: "memory")
#define CP_WAIT1()  asm volatile("cp.async.wait_group 1;" ::: "memory")

// split float4 into fp16 hi / fp16 lo (each packed as 2x half2 -> uint2)
__device__ __forceinline__ void split4h(float4 v, uint2& hi, uint2& lo) {
    __half hx = __float2half_rn(v.x);
    __half hy = __float2half_rn(v.y);
    __half hz = __float2half_rn(v.z);
    __half hw = __float2half_rn(v.w);
    __half lx = __float2half_rn(v.x - __half2float(hx));
    __half ly = __float2half_rn(v.y - __half2float(hy));
    __half lz = __float2half_rn(v.z - __half2float(hz));
    __half lw = __float2half_rn(v.w - __half2float(hw));
    __half2 h01 = __halves2half2(hx, hy);
    __half2 h23 = __halves2half2(hz, hw);
    __half2 l01 = __halves2half2(lx, ly);
    __half2 l23 = __halves2half2(lz, lw);
    hi.x = *reinterpret_cast<uint32_t*>(&h01);
    hi.y = *reinterpret_cast<uint32_t*>(&h23);
    lo.x = *reinterpret_cast<uint32_t*>(&l01);
    lo.y = *reinterpret_cast<uint32_t*>(&l23);
}

// ======================= K1: fused prep (balanced blocks) ===================
// blocks [0,1024):    x split for 4 timesteps -> g_ah/g_al, temporal partial
//                     plane, spatial-sum partials. blocks 0..7 zero BN accums.
// blocks [1024,2048): W split, 4 float4 per thread.
__global__ __launch_bounds__(256)
void prep_kernel(const float* __restrict__ x, const float* __restrict__ W) {
    const int tid = threadIdx.x;
    if (blockIdx.x >= 1024) {
        int base = (blockIdx.x - 1024) * 1024;
        #pragma unroll
        for (int i = 0; i < 4; i++) {
            int idx4 = base + i * 256 + tid;
            float4 v = reinterpret_cast<const float4*>(W)[idx4];
            uint2 hi, lo;
            split4h(v, hi, lo);
            reinterpret_cast<uint2*>(g_wh)[idx4] = hi;
            reinterpret_cast<uint2*>(g_wl)[idx4] = lo;
        }
        return;
    }

    // ---- x-side block: t-group tq (4 timesteps), column block cb ----
    const int tq = blockIdx.x >> 8;              // 0..3
    const int cb = blockIdx.x & 255;             // 0..255
    if (blockIdx.x < 8) {
        g_colsum[blockIdx.x * 256 + tid] = 0.f;
        g_colsq [blockIdx.x * 256 + tid] = 0.f;
    }

    __shared__ float red[4][8];
    const int idx4 = cb * 256 + tid;             // float4 index into [B,N]
    const int wid  = tid >> 5;
    const int lane = tid & 31;
    const float4* x4 = reinterpret_cast<const float4*>(x);
    uint2* ah2 = reinterpret_cast<uint2*>(g_ah);
    uint2* al2 = reinterpret_cast<uint2*>(g_al);

    float4 ts = make_float4(0.f, 0.f, 0.f, 0.f);
    #pragma unroll
    for (int tt = 0; tt < 4; tt++) {
        int t = tq * 4 + tt;
        size_t off = (size_t)t * (BN_ / 4) + idx4;
        float4 v = x4[off];
        ts.x += v.x; ts.y += v.y; ts.z += v.z; ts.w += v.w;
        uint2 hi, lo;
        split4h(v, hi, lo);
        ah2[off] = hi;
        al2[off] = lo;
        float s = v.x + v.y + v.z + v.w;
        #pragma unroll
        for (int o = 16; o > 0; o >>= 1)
            s += __shfl_down_sync(0xffffffffu, s, o);
        if (lane == 0) red[tt][wid] = s;
    }
    reinterpret_cast<float4*>(g_tsump)[tq * (BN_ / 4) + idx4] = ts;
    __syncthreads();
    if (tid < 4) {
        float s = 0.f;
        #pragma unroll
        for (int w = 0; w < 8; w++) s += red[tid][w];
        g_sspart[(tq * 4 + tid) * 256 + cb] = s;
    }
}

// ======================= K2: mma.sync fp16x3 GEMM (pre-split) ===============
// h[r,m] = sum_k x[r,k] * W[m,k].
// CTA tile 128(M) x 128(N) x 32(K), 256 threads = 8 warps (2x4), warp 64x32.
// fp16 planes pre-split in gmem; hot loop is pure cp.async + LDSM + MMA.
// Epilogue fuses BN column statistics via shfl-reduce + atomics.
#define BK      32
#define HPITCH  40                      // halfs per smem row (32 + 8 pad)
#define PLANEB  (128 * HPITCH * 2)      // 10240 bytes per plane
#define STAGEB  (4 * PLANEB)            // A_hi, A_lo, B_hi, B_lo: 40960 B
#define GEMM_SMEM (2 * STAGEB)          // 81920 bytes

__global__ __launch_bounds__(256, 2)
void gemm_mma_kernel(float* __restrict__ C) {
    extern __shared__ char smc[];
    const uint32_t sbase = smem_u32(smc);
    const int tid  = threadIdx.x;
    const int wid  = tid >> 5;
    const int lane = tid & 31;
    const int wm = wid >> 2;            // 0..1 -> 64-row slab
    const int wn = wid & 3;             // 0..3 -> 32-col slab
    const int rowBase = blockIdx.y * 128;
    const int colBase = blockIdx.x * 128;

    float acc[4][4][4];
    #pragma unroll
    for (int i = 0; i < 4; i++)
        #pragma unroll
        for (int j = 0; j < 4; j++)
            #pragma unroll
            for (int c = 0; c < 4; c++) acc[i][j][c] = 0.f;

    // ---- cp.async loader: thread -> (row, 16-half part) ----
    const int lrow = tid >> 1;                  // 0..127
    const int part = (tid & 1) * 16;            // half offset within row
    const __half* pAh = g_ah + (size_t)(rowBase + lrow) * N_ + part;
    const __half* pAl = g_al + (size_t)(rowBase + lrow) * N_ + part;
    const __half* pBh = g_wh + (size_t)(colBase + lrow) * N_ + part;
    const __half* pBl = g_wl + (size_t)(colBase + lrow) * N_ + part;
    const uint32_t dRow = (uint32_t)((lrow * HPITCH + part) * 2);

    // ---- ldmatrix per-lane byte offsets ----
    const uint32_t aLane = (uint32_t)((((lane & 15) * HPITCH) + (lane >> 4) * 8) * 2);
    const uint32_t bLane = (uint32_t)(((((lane & 7) + ((lane >> 4) & 1) * 8) * HPITCH)
                                       + ((lane >> 3) & 1) * 8) * 2);
    const uint32_t aBase = sbase + (uint32_t)((wm * 64) * HPITCH * 2) + aLane;
    const uint32_t bBase = sbase + 2 * PLANEB + (uint32_t)((wn * 32) * HPITCH * 2) + bLane;

    // ---- prologue: load chunks 0,1 ----
    #pragma unroll
    for (int s = 0; s < 2; s++) {
        const uint32_t d = sbase + s * STAGEB + dRow;
        const int ko = s * BK;
        CP_ASYNC16(d,                       pAh + ko);
        CP_ASYNC16(d + 16,                  pAh + ko + 8);
        CP_ASYNC16(d + PLANEB,              pAl + ko);
        CP_ASYNC16(d + PLANEB + 16,         pAl + ko + 8);
        CP_ASYNC16(d + 2 * PLANEB,          pBh + ko);
        CP_ASYNC16(d + 2 * PLANEB + 16,     pBh + ko + 8);
        CP_ASYNC16(d + 3 * PLANEB,          pBl + ko);
        CP_ASYNC16(d + 3 * PLANEB + 16,     pBl + ko + 8);
        CP_COMMIT();
    }

    const int NCHUNK = N_ / BK;          // 64
    #pragma unroll 1
    for (int kc = 0; kc < NCHUNK; kc++) {
        const int st = kc & 1;
        CP_WAIT1();
        __syncthreads();

        const uint32_t aS = aBase + st * STAGEB;
        const uint32_t bS = bBase + st * STAGEB;

        #pragma unroll
        for (int ks = 0; ks < 2; ks++) {
            const uint32_t kb = ks * 32;   // 16 halfs = 32 bytes
            uint32_t bh[2][4], bl[2][4];
            #pragma unroll
            for (int jp = 0; jp < 2; jp++) {
                ldsm_x4(bS + kb + jp * (16 * HPITCH * 2),
                        bh[jp][0], bh[jp][1], bh[jp][2], bh[jp][3]);
                ldsm_x4(bS + PLANEB + kb + jp * (16 * HPITCH * 2),
                        bl[jp][0], bl[jp][1], bl[jp][2], bl[jp][3]);
            }
            #pragma unroll
            for (int i = 0; i < 4; i++) {
                uint32_t ah[4], al[4];
                ldsm_x4(aS + kb + i * (16 * HPITCH * 2), ah[0], ah[1], ah[2], ah[3]);
                ldsm_x4(aS + PLANEB + kb + i * (16 * HPITCH * 2), al[0], al[1], al[2], al[3]);
                #pragma unroll
                for (int j = 0; j < 4; j++)
                    mma_fp16(acc[i][j], ah, bh[j >> 1][(j & 1) * 2], bh[j >> 1][(j & 1) * 2 + 1]);
                #pragma unroll
                for (int j = 0; j < 4; j++)
                    mma_fp16(acc[i][j], al, bh[j >> 1][(j & 1) * 2], bh[j >> 1][(j & 1) * 2 + 1]);
                #pragma unroll
                for (int j = 0; j < 4; j++)
                    mma_fp16(acc[i][j], ah, bl[j >> 1][(j & 1) * 2], bl[j >> 1][(j & 1) * 2 + 1]);
            }
        }
        __syncthreads();

        // refill the consumed stage with chunk kc+2
        if (kc + 2 < NCHUNK) {
            const uint32_t d = sbase + st * STAGEB + dRow;
            const int ko = (kc + 2) * BK;
            CP_ASYNC16(d,                       pAh + ko);
            CP_ASYNC16(d + 16,                  pAh + ko + 8);
            CP_ASYNC16(d + PLANEB,              pAl + ko);
            CP_ASYNC16(d + PLANEB + 16,         pAl + ko + 8);
            CP_ASYNC16(d + 2 * PLANEB,          pBh + ko);
            CP_ASYNC16(d + 2 * PLANEB + 16,     pBh + ko + 8);
            CP_ASYNC16(d + 3 * PLANEB,          pBl + ko);
            CP_ASYNC16(d + 3 * PLANEB + 16,     pBl + ko + 8);
        }
        CP_COMMIT();
    }

    // ---- epilogue: write 128x128 tile + fused BN column stats ----
    const int gid = lane >> 2;
    const int qd  = lane & 3;
    const int m0 = rowBase + wm * 64 + gid;
    const int n0 = colBase + wn * 32 + 2 * qd;
    #pragma unroll
    for (int i = 0; i < 4; i++) {
        #pragma unroll
        for (int jj = 0; jj < 4; jj++) {
            float* p = C + (size_t)(m0 + 16 * i) * N_ + n0 + 8 * jj;
            float2 v01 = make_float2(acc[i][jj][0], acc[i][jj][1]);
            float2 v23 = make_float2(acc[i][jj][2], acc[i][jj][3]);
            *reinterpret_cast<float2*>(p)          = v01;
            *reinterpret_cast<float2*>(p + 8 * N_) = v23;
        }
    }

    // column sums / sums-of-squares over this warp's 64 rows
    float s[4][2], q[4][2];
    #pragma unroll
    for (int j = 0; j < 4; j++) {
        s[j][0] = s[j][1] = q[j][0] = q[j][1] = 0.f;
        #pragma unroll
        for (int i = 0; i < 4; i++) {
            s[j][0] += acc[i][j][0] + acc[i][j][2];
            s[j][1] += acc[i][j][1] + acc[i][j][3];
            q[j][0] += acc[i][j][0] * acc[i][j][0] + acc[i][j][2] * acc[i][j][2];
            q[j][1] += acc[i][j][1] * acc[i][j][1] + acc[i][j][3] * acc[i][j][3];
        }
    }
    #pragma unroll
    for (int j = 0; j < 4; j++)
        #pragma unroll
        for (int c = 0; c < 2; c++) {
            #pragma unroll
            for (int off = 16; off >= 4; off >>= 1) {
                s[j][c] += __shfl_down_sync(0xffffffffu, s[j][c], off);
                q[j][c] += __shfl_down_sync(0xffffffffu, q[j][c], off);
            }
        }
    if (lane < 4) {
        #pragma unroll
        for (int j = 0; j < 4; j++)
            #pragma unroll
            for (int c = 0; c < 2; c++) {
                int col = colBase + wn * 32 + 2 * lane + 8 * j + c;
                atomicAdd(&g_colsum[col], s[j][c]);
                atomicAdd(&g_colsq[col],  q[j][c]);
            }
    }
}

// ======================= K3: fused BN + 3x LIF + combine ====================
__global__ __launch_bounds__(256)
void fused_lif_kernel(const float* __restrict__ x,
                      const float* __restrict__ gamma,
                      const float* __restrict__ beta,
                      float* __restrict__ out) {
    int idx4 = blockIdx.x * 256 + threadIdx.x;   // float4 index into [B,N]
    int b  = idx4 >> 9;
    int n4 = idx4 & 511;

    float4 cs4 = reinterpret_cast<const float4*>(g_colsum)[n4];
    float4 cq4 = reinterpret_cast<const float4*>(g_colsq)[n4];
    float4 ga4 = reinterpret_cast<const float4*>(gamma)[n4];
    float4 be4 = reinterpret_cast<const float4*>(beta)[n4];

    // temporal_sum = sum of 4 partial planes
    float4 ts4 = make_float4(0.f, 0.f, 0.f, 0.f);
    #pragma unroll
    for (int p = 0; p < 4; p++) {
        float4 v = reinterpret_cast<const float4*>(g_tsump)[p * (BN_ / 4) + idx4];
        ts4.x += v.x; ts4.y += v.y; ts4.z += v.z; ts4.w += v.w;
    }

    const float inv = 1.0f / TB_;
    float mu[4]    = {cs4.x * inv, cs4.y * inv, cs4.z * inv, cs4.w * inv};
    float var[4]   = {cq4.x * inv - mu[0] * mu[0], cq4.y * inv - mu[1] * mu[1],
                      cq4.z * inv - mu[2] * mu[2], cq4.w * inv - mu[3] * mu[3]};
    float scale[4] = {ga4.x * rsqrtf(var[0] + 1e-5f), ga4.y * rsqrtf(var[1] + 1e-5f),
                      ga4.z * rsqrtf(var[2] + 1e-5f), ga4.w * rsqrtf(var[3] + 1e-5f)};
    float bet[4]   = {be4.x, be4.y, be4.z, be4.w};
    float ts[4]    = {ts4.x, ts4.y, ts4.z, ts4.w};

    float v1[4] = {0, 0, 0, 0}, v2[4] = {0, 0, 0, 0}, v3[4] = {0, 0, 0, 0};
    const float4* h4 = reinterpret_cast<const float4*>(g_h);
    const float4* x4 = reinterpret_cast<const float4*>(x);
    float4* o4 = reinterpret_cast<float4*>(out);

    #pragma unroll
    for (int t = 0; t < T_; t++) {
        size_t off = (size_t)t * (BN_ / 4) + idx4;
        float4 hv = h4[off];
        float4 xv = x4[off];
        float hh[4] = {hv.x, hv.y, hv.z, hv.w};
        float xx[4] = {xv.x, xv.y, xv.z, xv.w};
        float ss = g_sspart[t * 256 + b * 2] + g_sspart[t * 256 + b * 2 + 1];
        float res[4];
        #pragma unroll
        for (int j = 0; j < 4; j++) {
            float hn = (hh[j] - mu[j]) * scale[j] + bet[j];
            v1[j] = 0.5f * v1[j] + hn;
            float s1 = (v1[j] >= 1.0f) ? 1.0f : 0.0f;
            v1[j] = (v1[j] >= 1.0f) ? 0.0f : v1[j];
            v2[j] = 0.5f * v2[j] + s1 * ss;
            float s2 = (v2[j] >= 1.0f) ? 1.0f : 0.0f;
            v2[j] = (v2[j] >= 1.0f) ? 0.0f : v2[j];
            v3[j] = 0.5f * v3[j] + s1 * ts[j];
            float s3 = (v3[j] >= 1.0f) ? 1.0f : 0.0f;
            v3[j] = (v3[j] >= 1.0f) ? 0.0f : v3[j];
            res[j] = xx[j] + s2 * s3;
        }
        o4[off] = make_float4(res[0], res[1], res[2], res[3]);
    }
}

// ======================= launch =============================================
extern "C" void kernel_launch(void* const* d_in, const int* in_sizes, int n_in,
                              void* d_out, int out_size) {
    const float* x     = (const float*)d_in[0];   // [T,B,N]
    const float* W     = (const float*)d_in[1];   // [N,N]
    const float* gamma = (const float*)d_in[2];
    const float* beta  = (const float*)d_in[3];
    float* out = (float*)d_out;

    float* h;
    cudaGetSymbolAddress((void**)&h, g_h);

    cudaFuncSetAttribute(gemm_mma_kernel,
                         cudaFuncAttributeMaxDynamicSharedMemorySize, GEMM_SMEM);

    prep_kernel<<<2048, 256>>>(x, W);

    dim3 gemmGrid(N_ / 128, TB_ / 128);           // 16 x 16 = 256 CTAs
    gemm_mma_kernel<<<gemmGrid, 256, GEMM_SMEM>>>(h);

    fused_lif_kernel<<<BN_ / 1024, 256>>>(x, gamma, beta, out);
}